// round 15
// baseline (speedup 1.0000x reference)
#include <cuda_runtime.h>
#include <cuda_bf16.h>
#include <cstdint>

// MaxAggregator: out[n, :] = max over s of features[neighbor_idx[n, s], :]
// N = 100000 nodes, S = 10 samples, D = 256 features (fp32).
//
// R15: champion R7 (8x32-col tiles, 8 thr/node, fp32) + TILE PAIRING:
// each block processes two adjacent 32-col tiles with ONE idx read.
// - idx LDG instructions per node halve (5 int2 serve 20 gathered loads)
// - grid halves (12500), less launch/tail overhead
// - tile A's values die before tile B's load -> regs stay ~36-40, occ ~84%
// - instantaneous slice footprint = 2 tiles = 25.6 MB, L2-resident.

#define NUM_SAMPLE 10
#define D_FEAT 256
#define N_PAIRS 4                          // 4 pairs of 32-col tiles
#define ROW_BYTES (D_FEAT * 4)             // 1024 B per feature row
#define THREADS_PER_NODE 8

__global__ void __launch_bounds__(256) max_agg_kernel(
    const int* __restrict__ neighbor_idx,   // [N, 10]
    const float* __restrict__ features,     // [U, 256]
    float* __restrict__ out,                // [N, 256]
    int n_nodes, int blocks_per_pair)
{
    int pair = blockIdx.x / blocks_per_pair;          // 0..3
    int bid_in_pair = blockIdx.x - pair * blocks_per_pair;

    int t = bid_in_pair * blockDim.x + threadIdx.x;   // < 800000
    int node  = t >> 3;
    int chunk = t & 7;
    if (node >= n_nodes) return;

    // byte offsets of this thread's float4 in tiles A and B of the pair
    uint32_t cbA = (uint32_t)(pair * 16 + chunk) * 16u;   // tile 2p
    uint32_t cbB = cbA + 128u;                            // tile 2p+1 (+32 cols)

    // idx row = 40 bytes -> 5x int2, read ONCE, serves both tiles.
    const int2* idx2 = (const int2*)(neighbor_idx + (long long)node * NUM_SAMPLE);
    int2 p0 = __ldg(idx2 + 0);
    int2 p1 = __ldg(idx2 + 1);
    int2 p2 = __ldg(idx2 + 2);
    int2 p3 = __ldg(idx2 + 3);
    int2 p4 = __ldg(idx2 + 4);

    const char* fbase = (const char*)features;

    // 32-bit row byte-offsets (table = 102.4 MB < 4 GB), reused for A and B.
    uint32_t r0 = (uint32_t)p0.x * ROW_BYTES;
    uint32_t r1 = (uint32_t)p0.y * ROW_BYTES;
    uint32_t r2 = (uint32_t)p1.x * ROW_BYTES;
    uint32_t r3 = (uint32_t)p1.y * ROW_BYTES;
    uint32_t r4 = (uint32_t)p2.x * ROW_BYTES;
    uint32_t r5 = (uint32_t)p2.y * ROW_BYTES;
    uint32_t r6 = (uint32_t)p3.x * ROW_BYTES;
    uint32_t r7 = (uint32_t)p3.y * ROW_BYTES;
    uint32_t r8 = (uint32_t)p4.x * ROW_BYTES;
    uint32_t r9 = (uint32_t)p4.y * ROW_BYTES;

    uint32_t obase = (uint32_t)node * ROW_BYTES;

    // ---------------- Tile A ----------------
    {
        float4 v0 = __ldg((const float4*)(fbase + r0 + cbA));
        float4 v1 = __ldg((const float4*)(fbase + r1 + cbA));
        float4 v2 = __ldg((const float4*)(fbase + r2 + cbA));
        float4 v3 = __ldg((const float4*)(fbase + r3 + cbA));
        float4 v4 = __ldg((const float4*)(fbase + r4 + cbA));
        float4 v5 = __ldg((const float4*)(fbase + r5 + cbA));
        float4 v6 = __ldg((const float4*)(fbase + r6 + cbA));
        float4 v7 = __ldg((const float4*)(fbase + r7 + cbA));
        float4 v8 = __ldg((const float4*)(fbase + r8 + cbA));
        float4 v9 = __ldg((const float4*)(fbase + r9 + cbA));

        float4 m;
        m.x = fmaxf(fmaxf(fmaxf(v0.x, v1.x), fmaxf(v2.x, v3.x)),
                    fmaxf(fmaxf(v4.x, v5.x), fmaxf(v6.x, v7.x)));
        m.y = fmaxf(fmaxf(fmaxf(v0.y, v1.y), fmaxf(v2.y, v3.y)),
                    fmaxf(fmaxf(v4.y, v5.y), fmaxf(v6.y, v7.y)));
        m.z = fmaxf(fmaxf(fmaxf(v0.z, v1.z), fmaxf(v2.z, v3.z)),
                    fmaxf(fmaxf(v4.z, v5.z), fmaxf(v6.z, v7.z)));
        m.w = fmaxf(fmaxf(fmaxf(v0.w, v1.w), fmaxf(v2.w, v3.w)),
                    fmaxf(fmaxf(v4.w, v5.w), fmaxf(v6.w, v7.w)));
        m.x = fmaxf(m.x, fmaxf(v8.x, v9.x));
        m.y = fmaxf(m.y, fmaxf(v8.y, v9.y));
        m.z = fmaxf(m.z, fmaxf(v8.z, v9.z));
        m.w = fmaxf(m.w, fmaxf(v8.w, v9.w));

        *(float4*)((char*)out + obase + cbA) = m;
    }

    // ---------------- Tile B ----------------
    {
        float4 v0 = __ldg((const float4*)(fbase + r0 + cbB));
        float4 v1 = __ldg((const float4*)(fbase + r1 + cbB));
        float4 v2 = __ldg((const float4*)(fbase + r2 + cbB));
        float4 v3 = __ldg((const float4*)(fbase + r3 + cbB));
        float4 v4 = __ldg((const float4*)(fbase + r4 + cbB));
        float4 v5 = __ldg((const float4*)(fbase + r5 + cbB));
        float4 v6 = __ldg((const float4*)(fbase + r6 + cbB));
        float4 v7 = __ldg((const float4*)(fbase + r7 + cbB));
        float4 v8 = __ldg((const float4*)(fbase + r8 + cbB));
        float4 v9 = __ldg((const float4*)(fbase + r9 + cbB));

        float4 m;
        m.x = fmaxf(fmaxf(fmaxf(v0.x, v1.x), fmaxf(v2.x, v3.x)),
                    fmaxf(fmaxf(v4.x, v5.x), fmaxf(v6.x, v7.x)));
        m.y = fmaxf(fmaxf(fmaxf(v0.y, v1.y), fmaxf(v2.y, v3.y)),
                    fmaxf(fmaxf(v4.y, v5.y), fmaxf(v6.y, v7.y)));
        m.z = fmaxf(fmaxf(fmaxf(v0.z, v1.z), fmaxf(v2.z, v3.z)),
                    fmaxf(fmaxf(v4.z, v5.z), fmaxf(v6.z, v7.z)));
        m.w = fmaxf(fmaxf(fmaxf(v0.w, v1.w), fmaxf(v2.w, v3.w)),
                    fmaxf(fmaxf(v4.w, v5.w), fmaxf(v6.w, v7.w)));
        m.x = fmaxf(m.x, fmaxf(v8.x, v9.x));
        m.y = fmaxf(m.y, fmaxf(v8.y, v9.y));
        m.z = fmaxf(m.z, fmaxf(v8.z, v9.z));
        m.w = fmaxf(m.w, fmaxf(v8.w, v9.w));

        *(float4*)((char*)out + obase + cbB) = m;
    }
}

extern "C" void kernel_launch(void* const* d_in, const int* in_sizes, int n_in,
                              void* d_out, int out_size) {
    const int* neighbor_idx = (const int*)d_in[0];       // [N, 10] int32
    const float* features   = (const float*)d_in[1];     // [U, 256] fp32
    float* out = (float*)d_out;

    int n_nodes = in_sizes[0] / NUM_SAMPLE;              // 100000

    long long threads_per_pair = (long long)n_nodes * THREADS_PER_NODE;  // 800K
    int block = 256;
    int blocks_per_pair = (int)((threads_per_pair + block - 1) / block); // 3125
    int grid = blocks_per_pair * N_PAIRS;                                // 12500

    max_agg_kernel<<<grid, block>>>(neighbor_idx, features, out,
                                    n_nodes, blocks_per_pair);
}

// round 16
// speedup vs baseline: 1.0041x; 1.0041x over previous
#include <cuda_runtime.h>
#include <cuda_bf16.h>
#include <cstdint>

// MaxAggregator: out[n, :] = max over s of features[neighbor_idx[n, s], :]
// N = 100000 nodes, S = 10 samples, D = 256 features (fp32).
//
// R16: tile pairing (R15) with a scheduling fence. Two adjacent 32-col
// tiles per block, ONE idx read, but the two tiles are processed in a
// #pragma unroll 1 loop so ptxas cannot front-batch 20 loads (R15: 48 regs,
// occ 55% -> 70us). Each iteration body == R7's proven 32-reg sequence.
// Pair-major grid keeps the 25.6MB pair slice L2-resident.

#define NUM_SAMPLE 10
#define D_FEAT 256
#define N_PAIRS 4                          // 4 pairs of 32-col tiles
#define ROW_BYTES (D_FEAT * 4)             // 1024 B per feature row
#define THREADS_PER_NODE 8

__global__ void __launch_bounds__(256) max_agg_kernel(
    const int* __restrict__ neighbor_idx,   // [N, 10]
    const float* __restrict__ features,     // [U, 256]
    float* __restrict__ out,                // [N, 256]
    int n_nodes, int blocks_per_pair)
{
    int pair = blockIdx.x / blocks_per_pair;          // 0..3
    int bid_in_pair = blockIdx.x - pair * blocks_per_pair;

    int t = bid_in_pair * blockDim.x + threadIdx.x;   // < 800000
    int node  = t >> 3;
    int chunk = t & 7;
    if (node >= n_nodes) return;

    // idx row = 40 bytes -> 5x int2, read ONCE for both tiles of the pair.
    const int2* idx2 = (const int2*)(neighbor_idx + (long long)node * NUM_SAMPLE);
    int2 p0 = __ldg(idx2 + 0);
    int2 p1 = __ldg(idx2 + 1);
    int2 p2 = __ldg(idx2 + 2);
    int2 p3 = __ldg(idx2 + 3);
    int2 p4 = __ldg(idx2 + 4);

    // 32-bit row byte-offsets (table = 102.4 MB < 4 GB).
    uint32_t r0 = (uint32_t)p0.x * ROW_BYTES;
    uint32_t r1 = (uint32_t)p0.y * ROW_BYTES;
    uint32_t r2 = (uint32_t)p1.x * ROW_BYTES;
    uint32_t r3 = (uint32_t)p1.y * ROW_BYTES;
    uint32_t r4 = (uint32_t)p2.x * ROW_BYTES;
    uint32_t r5 = (uint32_t)p2.y * ROW_BYTES;
    uint32_t r6 = (uint32_t)p3.x * ROW_BYTES;
    uint32_t r7 = (uint32_t)p3.y * ROW_BYTES;
    uint32_t r8 = (uint32_t)p4.x * ROW_BYTES;
    uint32_t r9 = (uint32_t)p4.y * ROW_BYTES;

    const char* fbase = (const char*)features;
    uint32_t obase = (uint32_t)node * ROW_BYTES;
    // byte offset of this thread's float4 in tile A of the pair
    uint32_t cb = (uint32_t)(pair * 16 + chunk) * 16u;

    // Scheduling fence: process the two tiles strictly sequentially so the
    // register peak stays at one tile's working set (R7-like, ~32+10 regs).
    #pragma unroll 1
    for (int h = 0; h < 2; h++, cb += 128u) {
        float4 v0 = __ldg((const float4*)(fbase + r0 + cb));
        float4 v1 = __ldg((const float4*)(fbase + r1 + cb));
        float4 v2 = __ldg((const float4*)(fbase + r2 + cb));
        float4 v3 = __ldg((const float4*)(fbase + r3 + cb));
        float4 v4 = __ldg((const float4*)(fbase + r4 + cb));
        float4 v5 = __ldg((const float4*)(fbase + r5 + cb));
        float4 v6 = __ldg((const float4*)(fbase + r6 + cb));
        float4 v7 = __ldg((const float4*)(fbase + r7 + cb));
        float4 v8 = __ldg((const float4*)(fbase + r8 + cb));
        float4 v9 = __ldg((const float4*)(fbase + r9 + cb));

        float4 m;
        m.x = fmaxf(fmaxf(fmaxf(v0.x, v1.x), fmaxf(v2.x, v3.x)),
                    fmaxf(fmaxf(v4.x, v5.x), fmaxf(v6.x, v7.x)));
        m.y = fmaxf(fmaxf(fmaxf(v0.y, v1.y), fmaxf(v2.y, v3.y)),
                    fmaxf(fmaxf(v4.y, v5.y), fmaxf(v6.y, v7.y)));
        m.z = fmaxf(fmaxf(fmaxf(v0.z, v1.z), fmaxf(v2.z, v3.z)),
                    fmaxf(fmaxf(v4.z, v5.z), fmaxf(v6.z, v7.z)));
        m.w = fmaxf(fmaxf(fmaxf(v0.w, v1.w), fmaxf(v2.w, v3.w)),
                    fmaxf(fmaxf(v4.w, v5.w), fmaxf(v6.w, v7.w)));
        m.x = fmaxf(m.x, fmaxf(v8.x, v9.x));
        m.y = fmaxf(m.y, fmaxf(v8.y, v9.y));
        m.z = fmaxf(m.z, fmaxf(v8.z, v9.z));
        m.w = fmaxf(m.w, fmaxf(v8.w, v9.w));

        *(float4*)((char*)out + obase + cb) = m;
    }
}

extern "C" void kernel_launch(void* const* d_in, const int* in_sizes, int n_in,
                              void* d_out, int out_size) {
    const int* neighbor_idx = (const int*)d_in[0];       // [N, 10] int32
    const float* features   = (const float*)d_in[1];     // [U, 256] fp32
    float* out = (float*)d_out;

    int n_nodes = in_sizes[0] / NUM_SAMPLE;              // 100000

    long long threads_per_pair = (long long)n_nodes * THREADS_PER_NODE;  // 800K
    int block = 256;
    int blocks_per_pair = (int)((threads_per_pair + block - 1) / block); // 3125
    int grid = blocks_per_pair * N_PAIRS;                                // 12500

    max_agg_kernel<<<grid, block>>>(neighbor_idx, features, out,
                                    n_nodes, blocks_per_pair);
}